// round 5
// baseline (speedup 1.0000x reference)
#include <cuda_runtime.h>

// Problem constants (fixed by the reference)
#define NN 1024   // grid size (rows of x)
#define MM 256    // measurements
#define BB 512    // batch (cols of x)
#define LL 10     // layers
#define BETA 0.01f

// Tiling
#define BR 64     // output rows per block
#define BC 32     // output cols per block
#define BK 16     // k-chunk

// Ping-pong x buffers (no cudaMalloc allowed)
__device__ float2 g_bufA[NN * BB];
__device__ float2 g_bufB[NN * BB];

__global__ __launch_bounds__(256, 2)
void lista_layer(const float* __restrict__ v_re, const float* __restrict__ v_im,
                 const float* __restrict__ W2_re, const float* __restrict__ W2_im,
                 const float* __restrict__ y_re,  const float* __restrict__ y_im,
                 int l)
{
    __shared__ float2 v1s[2 * NN - 1];     // 16376 B  Toeplitz generator
    __shared__ float2 as[BK][BR + 1];      //  8320 B  W2 tile (padded vs write conflicts)
    __shared__ float2 bs[BK][BC];          //  4096 B  y / x tile

    const float2* xin  = (l & 1) ? g_bufA : g_bufB;
    float2*       xout = (l & 1) ? g_bufB : g_bufA;

    const int tid = threadIdx.x;
    const int ty  = tid >> 4;   // 0..15  (row group)
    const int tx  = tid & 15;   // 0..15  (col group)
    const int rowBase = blockIdx.y * BR;
    const int colBase = blockIdx.x * BC;

    // Build v1 = [conj(flip(v_l)), v_l[1:]] in SMEM (length 2N-1).
    // v1s[N-1-j] = conj(v[j]); v1s[N-1+j] = v[j] for j>=1.
    if (l > 0) {
        const float* vr = v_re + (size_t)l * NN;
        const float* vi = v_im + (size_t)l * NN;
        for (int j = tid; j < NN; j += 256) {
            float re = vr[j], im = vi[j];
            v1s[NN - 1 - j] = make_float2(re, -im);
            if (j > 0) v1s[NN - 1 + j] = make_float2(re, im);
        }
    }
    // (visibility of v1s is covered by the first __syncthreads in phase 1)

    float2 acc[4][2];
#pragma unroll
    for (int i = 0; i < 4; i++)
#pragma unroll
        for (int j = 0; j < 2; j++) acc[i][j] = make_float2(0.f, 0.f);

    // ---------------- Phase 1: W2_l @ y  (K = M = 256) ----------------
    const float* w2r = W2_re + (size_t)l * NN * MM;
    const float* w2i = W2_im + (size_t)l * NN * MM;
    for (int m0 = 0; m0 < MM; m0 += BK) {
#pragma unroll
        for (int e = tid; e < BR * BK; e += 256) {
            int r  = e >> 4;
            int mm = e & 15;
            size_t g = (size_t)(rowBase + r) * MM + (m0 + mm);
            as[mm][r] = make_float2(w2r[g], w2i[g]);
        }
#pragma unroll
        for (int e = tid; e < BK * BC; e += 256) {
            int kk = e >> 5;
            int c  = e & 31;
            size_t g = (size_t)(m0 + kk) * BB + (colBase + c);
            bs[kk][c] = make_float2(y_re[g], y_im[g]);
        }
        __syncthreads();
#pragma unroll
        for (int kk = 0; kk < BK; kk++) {
            float2 a[4], b[2];
#pragma unroll
            for (int i = 0; i < 4; i++) a[i] = as[kk][ty + 16 * i];
#pragma unroll
            for (int j = 0; j < 2; j++) b[j] = bs[kk][tx + 16 * j];
#pragma unroll
            for (int i = 0; i < 4; i++)
#pragma unroll
                for (int j = 0; j < 2; j++) {
                    acc[i][j].x = fmaf(a[i].x,  b[j].x, acc[i][j].x);
                    acc[i][j].x = fmaf(-a[i].y, b[j].y, acc[i][j].x);
                    acc[i][j].y = fmaf(a[i].x,  b[j].y, acc[i][j].y);
                    acc[i][j].y = fmaf(a[i].y,  b[j].x, acc[i][j].y);
                }
        }
        __syncthreads();
    }

    // ---------------- Phase 2: Toeplitz(v_l) @ x  (K = N = 1024) ----------------
    if (l > 0) {
        for (int k0 = 0; k0 < NN; k0 += BK) {
#pragma unroll
            for (int e = tid; e < BK * BC; e += 256) {
                int kk = e >> 5;
                int c  = e & 31;
                bs[kk][c] = xin[(size_t)(k0 + kk) * BB + (colBase + c)];
            }
            __syncthreads();
            const int vbase = rowBase + ty + (NN - 1) - k0;  // v1 index for kk=0, i=0
#pragma unroll
            for (int kk = 0; kk < BK; kk++) {
                float2 a[4], b[2];
#pragma unroll
                for (int i = 0; i < 4; i++) a[i] = v1s[vbase + 16 * i - kk];
#pragma unroll
                for (int j = 0; j < 2; j++) b[j] = bs[kk][tx + 16 * j];
#pragma unroll
                for (int i = 0; i < 4; i++)
#pragma unroll
                    for (int j = 0; j < 2; j++) {
                        acc[i][j].x = fmaf(a[i].x,  b[j].x, acc[i][j].x);
                        acc[i][j].x = fmaf(-a[i].y, b[j].y, acc[i][j].x);
                        acc[i][j].y = fmaf(a[i].x,  b[j].y, acc[i][j].y);
                        acc[i][j].y = fmaf(a[i].y,  b[j].x, acc[i][j].y);
                    }
            }
            __syncthreads();
        }
    }

    // ---------------- Epilogue: complex soft-threshold + store ----------------
#pragma unroll
    for (int i = 0; i < 4; i++) {
        int r = rowBase + ty + 16 * i;
#pragma unroll
        for (int j = 0; j < 2; j++) {
            int c = colBase + tx + 16 * j;
            float2 z = acc[i][j];
            float mag = sqrtf(z.x * z.x + z.y * z.y);
            float s = fmaxf(mag - BETA, 0.f) / fmaxf(mag, 1e-30f);
            xout[(size_t)r * BB + c] = make_float2(z.x * s, z.y * s);
        }
    }
}

// Layout A (primary hypothesis): expected output = REAL PART of x, row-major,
// N*B float32 elements. (Complex64 -> float32 astype in the harness discards imag;
// consistent with d_out < 4MB deduced from the R1 crash.)
__global__ void finalize_real(float* __restrict__ dst)
{
    const float2* src = g_bufB;   // layer 9 (odd) writes g_bufB
    long i = (long)blockIdx.x * blockDim.x + threadIdx.x;
    if (i < (long)NN * BB) dst[i] = src[i].x;
}

// Layout B: full interleaved (re,im) float view, 2*N*B floats, capped at n.
__global__ void finalize_interleaved(float* __restrict__ dst, long n)
{
    const float* src = (const float*)g_bufB;
    long i = (long)blockIdx.x * blockDim.x + threadIdx.x;
    long total = 2L * NN * BB;
    if (i < n && i < total) dst[i] = src[i];
}

extern "C" void kernel_launch(void* const* d_in, const int* in_sizes, int n_in,
                              void* d_out, int out_size)
{
    // Bind inputs by element count:
    //   v_*  : L*N = 10240      W2_* : L*N*M = 2621440      y_* : M*B = 131072
    // Assume metadata order = dict insertion order (v_re, v_im, W2_re, W2_im,
    // y_re, y_im): within each size class, FIRST occurrence is the REAL part.
    const float *v_re = 0, *v_im = 0, *W2_re = 0, *W2_im = 0, *y_re = 0, *y_im = 0;
    const long SV = (long)LL * NN, SW = (long)LL * NN * MM, SY = (long)MM * BB;
    for (int i = 0; i < n_in; i++) {
        const float* p = (const float*)d_in[i];
        long sz = in_sizes[i];
        if (sz == SV || sz == 4 * SV)      { if (!v_re)  v_re  = p; else v_im  = p; }
        else if (sz == SW || sz == 4 * SW) { if (!W2_re) W2_re = p; else W2_im = p; }
        else if (sz == SY || sz == 4 * SY) { if (!y_re)  y_re  = p; else y_im  = p; }
    }
    if (!v_re || !v_im || !W2_re || !W2_im || !y_re || !y_im) return;

    dim3 grid(BB / BC, NN / BR);   // (16, 16) = 256 blocks
    for (int l = 0; l < LL; l++) {
        lista_layer<<<grid, 256>>>(v_re, v_im, W2_re, W2_im, y_re, y_im, l);
    }

    const long NB = (long)NN * BB;            // 524288
    long os = out_size;
    if (os == NB || os == 4 * NB) {
        // out = real part, N*B float32 (element count, or same as byte count)
        finalize_real<<<(int)((NB + 255) / 256), 256>>>((float*)d_out);
    } else if (os == 2 * NB || os == 8 * NB) {
        // out = interleaved complex view, 2*N*B floats
        finalize_interleaved<<<(int)((2 * NB + 255) / 256), 256>>>((float*)d_out, 2 * NB);
    } else {
        // Unknown: write capped interleaved view (never exceeds out_size floats)
        long nf = os < 2 * NB ? os : 2 * NB;
        finalize_interleaved<<<(int)((nf + 255) / 256), 256>>>((float*)d_out, nf);
    }
}